// round 6
// baseline (speedup 1.0000x reference)
#include <cuda_runtime.h>
#include <math.h>

// ---------------------------------------------------------------------------
// Problem constants (shapes fixed by setup_inputs)
// ---------------------------------------------------------------------------
#define B_SZ   2
#define C_SZ   128
#define S_SZ   262144          // 64*64*64 voxels per (b,c)
#define NPAIR  (B_SZ * C_SZ)   // 256
#define NCHUNK 8
#define GBASES 8               // GRID_SIZE + SPLINE_ORDER = 5 + 3

#define TILE_VOX   256                    // voxels per fused tile
#define TILE_V4    (TILE_VOX / 4)         // 64 float4 lanes
#define TILES_PER_B (S_SZ / TILE_VOX)     // 1024

// Scratch (no device allocation allowed)
__device__ float g_psum[NPAIR * NCHUNK];
__device__ float g_pmax[NPAIR * NCHUNK];
__device__ float g_att[NPAIR];   // sigmoid channel attention per (b,c)
__device__ float g_wc[NPAIR];    // att * conv_w  per (b,c)

// ---------------------------------------------------------------------------
// Cox-de Boor B-spline bases, k=3, grid = arange(-3,9)*0.4 - 1  (12 knots).
// Uniform grid -> FDIV replaced by multiply with compile-time reciprocals.
// ---------------------------------------------------------------------------
__device__ __forceinline__ void bspline8(float x, float* __restrict__ out) {
    float grid[12];
#pragma unroll
    for (int i = 0; i < 12; i++) grid[i] = (float)(i - 3) * 0.4f - 1.0f;
    float b[11];
#pragma unroll
    for (int j = 0; j < 11; j++)
        b[j] = (x >= grid[j] && x < grid[j + 1]) ? 1.0f : 0.0f;
    const float inv[3] = {2.5f, 1.25f, 1.0f / 1.2f};
#pragma unroll
    for (int j = 1; j <= 3; j++) {
        const float r = inv[j - 1];
#pragma unroll
        for (int m = 0; m < 11; m++) {
            if (m < 11 - j) {
                b[m] = (x - grid[m]) * r * b[m]
                     + (grid[m + j + 1] - x) * r * b[m + 1];
            }
        }
    }
#pragma unroll
    for (int g = 0; g < GBASES; g++) out[g] = b[g];
}

__device__ __forceinline__ float siluf(float v) { return v * (1.0f / (1.0f + __expf(-v))); }
__device__ __forceinline__ float sigmoidf_(float v) { return 1.0f / (1.0f + __expf(-v)); }

// ---------------------------------------------------------------------------
// Kernel 1: per-(b,c) partial sum/max pooling. ~84% DRAM — leave as is.
// ---------------------------------------------------------------------------
__global__ void __launch_bounds__(256) pool_kernel(const float* __restrict__ x) {
    const int pair  = blockIdx.x >> 3;
    const int chunk = blockIdx.x & 7;
    const float4* p = (const float4*)(x + (size_t)pair * S_SZ + (size_t)chunk * (S_SZ / NCHUNK));

    float s = 0.0f, m = -3.4e38f;
#pragma unroll 4
    for (int it = 0; it < (S_SZ / NCHUNK / 4) / 256; it++) {
        float4 v = __ldcs(&p[it * 256 + threadIdx.x]);
        s += (v.x + v.y) + (v.z + v.w);
        m = fmaxf(m, fmaxf(fmaxf(v.x, v.y), fmaxf(v.z, v.w)));
    }
#pragma unroll
    for (int o = 16; o; o >>= 1) {
        s += __shfl_xor_sync(0xffffffffu, s, o);
        m = fmaxf(m, __shfl_xor_sync(0xffffffffu, m, o));
    }
    __shared__ float ss[8], sm[8];
    const int w = threadIdx.x >> 5, l = threadIdx.x & 31;
    if (l == 0) { ss[w] = s; sm[w] = m; }
    __syncthreads();
    if (threadIdx.x == 0) {
        float ts = 0.0f, tm = -3.4e38f;
#pragma unroll
        for (int i = 0; i < 8; i++) { ts += ss[i]; tm = fmaxf(tm, sm[i]); }
        g_psum[blockIdx.x] = ts;
        g_pmax[blockIdx.x] = tm;
    }
}

// ---------------------------------------------------------------------------
// Kernel 2: channel attention MLP (tiny). 1 block, 256 threads.
// ---------------------------------------------------------------------------
__global__ void __launch_bounds__(256) att_kernel(
    const float* __restrict__ ck1b,   // [8,128]
    const float* __restrict__ ck1s,   // [8,128,8]
    const float* __restrict__ ck2b,   // [128,8]
    const float* __restrict__ ck2s,   // [128,8,8]
    const float* __restrict__ convw)  // [128]
{
    __shared__ float s_val[512];            // [src(2)][pair(256)]
    __shared__ float s_silu[512];
    __shared__ float s_bas[512][GBASES];
    __shared__ float s_h1silu[32];          // [src][b][r]
    __shared__ float s_h1bas[32][GBASES];
    __shared__ float s_out[512];

    const int tid = threadIdx.x;

    // phase 0: reduce pooling partials
    {
        float ts = 0.0f, tm = -3.4e38f;
#pragma unroll
        for (int k = 0; k < NCHUNK; k++) {
            ts += g_psum[tid * NCHUNK + k];
            tm = fmaxf(tm, g_pmax[tid * NCHUNK + k]);
        }
        s_val[tid]       = ts * (1.0f / (float)S_SZ);  // y_avg
        s_val[256 + tid] = tm;                          // y_max
    }
    __syncthreads();

    // phase 1: silu + bases for all 512 pooled values
    for (int q = tid; q < 512; q += 256) {
        float v = s_val[q];
        s_silu[q] = siluf(v);
        bspline8(v, s_bas[q]);
    }
    __syncthreads();

    // phase 2: layer 1 -> h1 (32 tasks: src x b x r)
    if (tid < 32) {
        const int src = tid >> 4, b = (tid >> 3) & 1, r = tid & 7;
        const int base = src * 256 + b * 128;
        float acc = 0.0f;
        for (int i = 0; i < C_SZ; i++) {
            const int q = base + i;
            acc += s_silu[q] * ck1b[r * C_SZ + i];
            const float* sw = ck1s + (r * C_SZ + i) * GBASES;
#pragma unroll
            for (int g = 0; g < GBASES; g++) acc += s_bas[q][g] * sw[g];
        }
        const float hv = fmaxf(acc, 0.0f);
        s_h1silu[tid] = siluf(hv);
        bspline8(hv, s_h1bas[tid]);
    }
    __syncthreads();

    // phase 3: layer 2 (512 tasks: src x b x c)
    for (int q = tid; q < 512; q += 256) {
        const int src = q >> 8, b = (q >> 7) & 1, c = q & 127;
        float acc = 0.0f;
#pragma unroll
        for (int r = 0; r < 8; r++) {
            const int hq = src * 16 + b * 8 + r;
            acc += s_h1silu[hq] * ck2b[c * 8 + r];
            const float* sw = ck2s + (c * 8 + r) * GBASES;
#pragma unroll
            for (int g = 0; g < GBASES; g++) acc += s_h1bas[hq][g] * sw[g];
        }
        s_out[q] = acc;
    }
    __syncthreads();

    // phase 4: combine avg+max, sigmoid, and fold in conv_w
    {
        const float a = sigmoidf_(s_out[tid] + s_out[256 + tid]);
        g_att[tid] = a;
        g_wc[tid]  = a * convw[tid & 127];
    }
}

// ---------------------------------------------------------------------------
// Kernel 3: fused spatial pass — BIG TILE + L2 REUSE.
// Tile = 256 voxels x 128 channels (128 KB). 512 threads:
//   lane = tid&63 (64 float4 lanes), cpg = tid>>6 in [0,8), 16 channels each.
// Phase A: stream tile with __ldcg (keep in L2), 1 KB contiguous per channel,
//          accumulate ws only (no register tile).
// Spline:  256 threads, one voxel each.
// Phase B: re-read tile (__ldcs, L2-hit, evict), scale, stream out.
// Residency capped at 4 blocks/SM via 38 KB dummy dynamic smem so that all
// in-flight tiles (148*4*128KB = 75 MB) fit in L2 until their phase B.
// ---------------------------------------------------------------------------
__global__ void __launch_bounds__(512) fused_kernel(
    const float* __restrict__ x,
    const float* __restrict__ skb,   // [1]
    const float* __restrict__ sks,   // [8]
    float* __restrict__ out)
{
    __shared__ float4 wred[8][TILE_V4];              // 8 KB partial y_spatial
    __shared__ __align__(16) float satts[TILE_VOX];  // 1 KB spatial attention
    __shared__ float att_s[C_SZ];                    // channel att
    __shared__ float wc_s[C_SZ];                     // att * conv_w

    const int b    = blockIdx.x >> 10;               // TILES_PER_B = 1024
    const int tile = blockIdx.x & (TILES_PER_B - 1);
    const int lane = threadIdx.x & (TILE_V4 - 1);
    const int cpg  = threadIdx.x >> 6;               // 0..7, 16 channels each

    if (threadIdx.x < C_SZ) {
        att_s[threadIdx.x] = g_att[b * C_SZ + threadIdx.x];
        wc_s[threadIdx.x]  = g_wc[b * C_SZ + threadIdx.x];
    }

    const size_t sbase4 = (size_t)tile * TILE_V4;    // float4 offset in plane
    const float4* xp = (const float4*)x;
    float4* op = (float4*)out;

    // Phase A: accumulate spatial partial sums; tile lands in L2.
    float4 ws = make_float4(0.f, 0.f, 0.f, 0.f);
    const int cbase = cpg * 16;
    __syncthreads();                                  // att_s/wc_s ready
#pragma unroll
    for (int k = 0; k < 16; k++) {
        const int c = cbase + k;
        const size_t idx = (((size_t)(b * C_SZ + c)) << 16) + sbase4 + (size_t)lane;
        const float4 v = __ldcg(&xp[idx]);
        const float wc = wc_s[c];
        ws.x += v.x * wc; ws.y += v.y * wc; ws.z += v.z * wc; ws.w += v.w * wc;
    }
    wred[cpg][lane] = ws;
    __syncthreads();

    // Spline: 256 threads, one voxel each.
    if (threadIdx.x < TILE_VOX) {
        const int vox = threadIdx.x;
        const int l4  = vox >> 2, j = vox & 3;
        float y = 0.0f;
#pragma unroll
        for (int p = 0; p < 8; p++) y += ((const float*)&wred[p][l4])[j];

        float bas[GBASES];
        bspline8(y, bas);
        float acc = siluf(y) * skb[0];
#pragma unroll
        for (int g = 0; g < GBASES; g++) acc += bas[g] * sks[g];
        satts[vox] = sigmoidf_(acc);
    }
    __syncthreads();

    // Phase B: re-read the tile from L2, scale, stream out.
    const float4 sa = ((const float4*)satts)[lane];
#pragma unroll
    for (int k = 0; k < 16; k++) {
        const int c = cbase + k;
        const size_t idx = (((size_t)(b * C_SZ + c)) << 16) + sbase4 + (size_t)lane;
        const float4 v = __ldcs(&xp[idx]);
        const float a  = att_s[c];
        __stcs(&op[idx], make_float4(v.x * a * sa.x, v.y * a * sa.y,
                                     v.z * a * sa.z, v.w * a * sa.w));
    }
}

// ---------------------------------------------------------------------------
// Launch
// ---------------------------------------------------------------------------
extern "C" void kernel_launch(void* const* d_in, const int* in_sizes, int n_in,
                              void* d_out, int out_size) {
    const float* x     = (const float*)d_in[0];
    const float* ck1b  = (const float*)d_in[1];
    const float* ck1s  = (const float*)d_in[2];
    const float* ck2b  = (const float*)d_in[3];
    const float* ck2s  = (const float*)d_in[4];
    const float* convw = (const float*)d_in[5];
    const float* skb   = (const float*)d_in[6];
    const float* sks   = (const float*)d_in[7];
    float* out = (float*)d_out;

    pool_kernel<<<NPAIR * NCHUNK, 256>>>(x);
    att_kernel<<<1, 256>>>(ck1b, ck1s, ck2b, ck2s, convw);
    // 38 KB dummy dynamic smem: caps residency at 4 blocks/SM so all
    // in-flight tiles stay L2-resident between phase A and phase B.
    fused_kernel<<<B_SZ * TILES_PER_B, 512, 38 * 1024>>>(x, skb, sks, out);
}

// round 7
// speedup vs baseline: 1.1028x; 1.1028x over previous
#include <cuda_runtime.h>
#include <math.h>

// ---------------------------------------------------------------------------
// Problem constants (shapes fixed by setup_inputs)
// ---------------------------------------------------------------------------
#define B_SZ   2
#define C_SZ   128
#define S_SZ   262144          // 64*64*64 voxels per (b,c)
#define NPAIR  (B_SZ * C_SZ)   // 256
#define NCHUNK 8
#define GBASES 8               // GRID_SIZE + SPLINE_ORDER = 5 + 3
#define POOL_BLOCKS (NPAIR * NCHUNK)   // 2048

#define TILE_VOX 128                   // voxels per fused tile
#define TILE_V4  32                    // float4 lanes per tile
#define TILES_PER_B (S_SZ / TILE_VOX)  // 2048

// Scratch (no device allocation allowed)
__device__ float g_psum[NPAIR * NCHUNK];
__device__ float g_pmax[NPAIR * NCHUNK];
__device__ float g_att[NPAIR];   // sigmoid channel attention per (b,c)
__device__ float g_wc[NPAIR];    // att * conv_w  per (b,c)
__device__ unsigned g_ctr = 0;   // last-block counter (self-resetting)

// ---------------------------------------------------------------------------
// Cox-de Boor B-spline bases, k=3, grid = arange(-3,9)*0.4 - 1  (12 knots).
// Uniform grid -> FDIV replaced by multiply with compile-time reciprocals.
// ---------------------------------------------------------------------------
__device__ __forceinline__ void bspline8(float x, float* __restrict__ out) {
    float grid[12];
#pragma unroll
    for (int i = 0; i < 12; i++) grid[i] = (float)(i - 3) * 0.4f - 1.0f;
    float b[11];
#pragma unroll
    for (int j = 0; j < 11; j++)
        b[j] = (x >= grid[j] && x < grid[j + 1]) ? 1.0f : 0.0f;
    const float inv[3] = {2.5f, 1.25f, 1.0f / 1.2f};
#pragma unroll
    for (int j = 1; j <= 3; j++) {
        const float r = inv[j - 1];
#pragma unroll
        for (int m = 0; m < 11; m++) {
            if (m < 11 - j) {
                b[m] = (x - grid[m]) * r * b[m]
                     + (grid[m + j + 1] - x) * r * b[m + 1];
            }
        }
    }
#pragma unroll
    for (int g = 0; g < GBASES; g++) out[g] = b[g];
}

__device__ __forceinline__ float siluf(float v) { return v * (1.0f / (1.0f + __expf(-v))); }
__device__ __forceinline__ float sigmoidf_(float v) { return 1.0f / (1.0f + __expf(-v)); }

// ---------------------------------------------------------------------------
// Kernel 1: pooling + (last block) channel-attention MLP, fused via
// self-resetting last-block pattern. 2048 blocks x 256 threads.
// ---------------------------------------------------------------------------
__global__ void __launch_bounds__(256) pool_att_kernel(
    const float* __restrict__ x,
    const float* __restrict__ ck1b,   // [8,128]
    const float* __restrict__ ck1s,   // [8,128,8]
    const float* __restrict__ ck2b,   // [128,8]
    const float* __restrict__ ck2s,   // [128,8,8]
    const float* __restrict__ convw)  // [128]
{
    const int tid = threadIdx.x;

    // ---- pooling phase ----
    {
        const int pair  = blockIdx.x >> 3;
        const int chunk = blockIdx.x & 7;
        const float4* p = (const float4*)(x + (size_t)pair * S_SZ
                                            + (size_t)chunk * (S_SZ / NCHUNK));
        float s = 0.0f, m = -3.4e38f;
#pragma unroll 4
        for (int it = 0; it < (S_SZ / NCHUNK / 4) / 256; it++) {
            float4 v = __ldcs(&p[it * 256 + tid]);
            s += (v.x + v.y) + (v.z + v.w);
            m = fmaxf(m, fmaxf(fmaxf(v.x, v.y), fmaxf(v.z, v.w)));
        }
#pragma unroll
        for (int o = 16; o; o >>= 1) {
            s += __shfl_xor_sync(0xffffffffu, s, o);
            m = fmaxf(m, __shfl_xor_sync(0xffffffffu, m, o));
        }
        __shared__ float ss[8], sm[8];
        const int w = tid >> 5, l = tid & 31;
        if (l == 0) { ss[w] = s; sm[w] = m; }
        __syncthreads();
        if (tid == 0) {
            float ts = 0.0f, tm = -3.4e38f;
#pragma unroll
            for (int i = 0; i < 8; i++) { ts += ss[i]; tm = fmaxf(tm, sm[i]); }
            g_psum[blockIdx.x] = ts;
            g_pmax[blockIdx.x] = tm;
        }
    }

    // ---- elect the last block ----
    __shared__ int is_last;
    if (tid == 0) {
        __threadfence();
        unsigned old = atomicAdd(&g_ctr, 1u);
        is_last = (old == POOL_BLOCKS - 1u);
    }
    __syncthreads();
    if (!is_last) return;
    __threadfence();  // acquire: see all blocks' g_psum/g_pmax

    // ---- channel attention MLP (one block, 256 threads) ----
    __shared__ float s_val[512];            // [src(2)][pair(256)]
    __shared__ float s_silu[512];
    __shared__ float s_bas[512][GBASES];
    __shared__ float s_h1silu[32];          // [src][b][r]
    __shared__ float s_h1bas[32][GBASES];
    __shared__ float s_out[512];

    {
        float ts = 0.0f, tm = -3.4e38f;
#pragma unroll
        for (int k = 0; k < NCHUNK; k++) {
            ts += g_psum[tid * NCHUNK + k];
            tm = fmaxf(tm, g_pmax[tid * NCHUNK + k]);
        }
        s_val[tid]       = ts * (1.0f / (float)S_SZ);  // y_avg
        s_val[256 + tid] = tm;                          // y_max
    }
    __syncthreads();

    for (int q = tid; q < 512; q += 256) {
        float v = s_val[q];
        s_silu[q] = siluf(v);
        bspline8(v, s_bas[q]);
    }
    __syncthreads();

    if (tid < 32) {
        const int src = tid >> 4, b = (tid >> 3) & 1, r = tid & 7;
        const int base = src * 256 + b * 128;
        float acc = 0.0f;
        for (int i = 0; i < C_SZ; i++) {
            const int q = base + i;
            acc += s_silu[q] * ck1b[r * C_SZ + i];
            const float* sw = ck1s + (r * C_SZ + i) * GBASES;
#pragma unroll
            for (int g = 0; g < GBASES; g++) acc += s_bas[q][g] * sw[g];
        }
        const float hv = fmaxf(acc, 0.0f);
        s_h1silu[tid] = siluf(hv);
        bspline8(hv, s_h1bas[tid]);
    }
    __syncthreads();

    for (int q = tid; q < 512; q += 256) {
        const int src = q >> 8, b = (q >> 7) & 1, c = q & 127;
        float acc = 0.0f;
#pragma unroll
        for (int r = 0; r < 8; r++) {
            const int hq = src * 16 + b * 8 + r;
            acc += s_h1silu[hq] * ck2b[c * 8 + r];
            const float* sw = ck2s + (c * 8 + r) * GBASES;
#pragma unroll
            for (int g = 0; g < GBASES; g++) acc += s_h1bas[hq][g] * sw[g];
        }
        s_out[q] = acc;
    }
    __syncthreads();

    {
        const float a = sigmoidf_(s_out[tid] + s_out[256 + tid]);
        g_att[tid] = a;
        g_wc[tid]  = a * convw[tid & 127];
    }
    if (tid == 0) g_ctr = 0;   // reset for next graph replay
}

// ---------------------------------------------------------------------------
// Kernel 2: fused spatial pass — WARP-CONTIGUOUS 512B segments.
// Tile = 128 voxels x 128 channels. 512 threads = 16 warps:
//   warp w owns channels [8w, 8w+8), lane l covers float4 lane l (32 lanes =
//   128 voxels). Every LDG/STG: one warp moves 512 B contiguous from ONE
//   channel. Register tile va[8] (x * channel_att) survives both barriers.
// ---------------------------------------------------------------------------
__global__ void __launch_bounds__(512, 2) fused_kernel(
    const float* __restrict__ x,
    const float* __restrict__ skb,   // [1]
    const float* __restrict__ sks,   // [8]
    float* __restrict__ out)
{
    __shared__ float4 wred[16][TILE_V4];             // 8 KB partial y_spatial
    __shared__ __align__(16) float satts[TILE_VOX];  // per-voxel spatial att

    const int b    = blockIdx.x >> 11;               // TILES_PER_B = 2048
    const int tile = blockIdx.x & (TILES_PER_B - 1);
    const int w    = threadIdx.x >> 5;               // warp 0..15
    const int l    = threadIdx.x & 31;               // float4 lane

    const size_t sbase4 = (size_t)tile * TILE_V4;    // float4 offset in plane
    const float4* xp = (const float4*)x;
    float4* op = (float4*)out;

    float4 va[8];                                     // x * channel_att (regs)
    float4 ws = make_float4(0.f, 0.f, 0.f, 0.f);
    const int cbase = w * 8;
#pragma unroll
    for (int k = 0; k < 8; k++) {
        const int pair = b * C_SZ + cbase + k;
        const float4 v = __ldcs(&xp[((size_t)pair << 16) + sbase4 + (size_t)l]);
        const float a  = g_att[pair];                 // uniform per warp
        const float wc = g_wc[pair];
        va[k] = make_float4(v.x * a, v.y * a, v.z * a, v.w * a);
        ws.x += v.x * wc; ws.y += v.y * wc; ws.z += v.z * wc; ws.w += v.w * wc;
    }
    wred[w][l] = ws;
    __syncthreads();

    // 128 threads: one voxel each — reduce 16 partials, 1->1 KAN spline.
    if (threadIdx.x < TILE_VOX) {
        const int vox = threadIdx.x;
        const int l4  = vox >> 2, j = vox & 3;
        float y = 0.0f;
#pragma unroll
        for (int p = 0; p < 16; p++) y += ((const float*)&wred[p][l4])[j];

        float bas[GBASES];
        bspline8(y, bas);
        float acc = siluf(y) * skb[0];
#pragma unroll
        for (int g = 0; g < GBASES; g++) acc += bas[g] * sks[g];
        satts[vox] = sigmoidf_(acc);
    }
    __syncthreads();

    const float4 sa = ((const float4*)satts)[l];
#pragma unroll
    for (int k = 0; k < 8; k++) {
        const int pair = b * C_SZ + cbase + k;
        __stcs(&op[((size_t)pair << 16) + sbase4 + (size_t)l],
               make_float4(va[k].x * sa.x, va[k].y * sa.y,
                           va[k].z * sa.z, va[k].w * sa.w));
    }
}

// ---------------------------------------------------------------------------
// Launch
// ---------------------------------------------------------------------------
extern "C" void kernel_launch(void* const* d_in, const int* in_sizes, int n_in,
                              void* d_out, int out_size) {
    const float* x     = (const float*)d_in[0];
    const float* ck1b  = (const float*)d_in[1];
    const float* ck1s  = (const float*)d_in[2];
    const float* ck2b  = (const float*)d_in[3];
    const float* ck2s  = (const float*)d_in[4];
    const float* convw = (const float*)d_in[5];
    const float* skb   = (const float*)d_in[6];
    const float* sks   = (const float*)d_in[7];
    float* out = (float*)d_out;

    pool_att_kernel<<<POOL_BLOCKS, 256>>>(x, ck1b, ck1s, ck2b, ck2s, convw);
    fused_kernel<<<B_SZ * TILES_PER_B, 512>>>(x, skb, sks, out);
}

// round 8
// speedup vs baseline: 1.1867x; 1.0761x over previous
#include <cuda_runtime.h>
#include <math.h>

// ---------------------------------------------------------------------------
// Problem constants (shapes fixed by setup_inputs)
// ---------------------------------------------------------------------------
#define B_SZ   2
#define C_SZ   128
#define S_SZ   262144          // 64*64*64 voxels per (b,c)
#define NPAIR  (B_SZ * C_SZ)   // 256
#define NCHUNK 8
#define GBASES 8               // GRID_SIZE + SPLINE_ORDER = 5 + 3

#define TILE_VOX 128                   // voxels per fused tile
#define TILE_V4  32                    // float4 lanes per tile
#define TILES_PER_B (S_SZ / TILE_VOX)  // 2048

// Scratch (no device allocation allowed)
__device__ float g_psum[NPAIR * NCHUNK];
__device__ float g_pmax[NPAIR * NCHUNK];
__device__ float g_att[NPAIR];   // sigmoid channel attention per (b,c)
__device__ float g_wc[NPAIR];    // att * conv_w  per (b,c)

// ---------------------------------------------------------------------------
// Cox-de Boor B-spline bases, k=3, grid = arange(-3,9)*0.4 - 1  (12 knots).
// Uniform grid -> FDIV replaced by multiply with compile-time reciprocals.
// ---------------------------------------------------------------------------
__device__ __forceinline__ void bspline8(float x, float* __restrict__ out) {
    float grid[12];
#pragma unroll
    for (int i = 0; i < 12; i++) grid[i] = (float)(i - 3) * 0.4f - 1.0f;
    float b[11];
#pragma unroll
    for (int j = 0; j < 11; j++)
        b[j] = (x >= grid[j] && x < grid[j + 1]) ? 1.0f : 0.0f;
    const float inv[3] = {2.5f, 1.25f, 1.0f / 1.2f};
#pragma unroll
    for (int j = 1; j <= 3; j++) {
        const float r = inv[j - 1];
#pragma unroll
        for (int m = 0; m < 11; m++) {
            if (m < 11 - j) {
                b[m] = (x - grid[m]) * r * b[m]
                     + (grid[m + j + 1] - x) * r * b[m + 1];
            }
        }
    }
#pragma unroll
    for (int g = 0; g < GBASES; g++) out[g] = b[g];
}

__device__ __forceinline__ float siluf(float v) { return v * (1.0f / (1.0f + __expf(-v))); }
__device__ __forceinline__ float sigmoidf_(float v) { return 1.0f / (1.0f + __expf(-v)); }

// ---------------------------------------------------------------------------
// Kernel 1: per-(b,c) partial sum/max pooling. 27 regs, ~84% DRAM.
// Kept separate from the MLP so the streaming phase keeps full occupancy.
// ---------------------------------------------------------------------------
__global__ void __launch_bounds__(256) pool_kernel(const float* __restrict__ x) {
    const int pair  = blockIdx.x >> 3;
    const int chunk = blockIdx.x & 7;
    const float4* p = (const float4*)(x + (size_t)pair * S_SZ + (size_t)chunk * (S_SZ / NCHUNK));

    float s = 0.0f, m = -3.4e38f;
#pragma unroll 4
    for (int it = 0; it < (S_SZ / NCHUNK / 4) / 256; it++) {
        float4 v = __ldcs(&p[it * 256 + threadIdx.x]);
        s += (v.x + v.y) + (v.z + v.w);
        m = fmaxf(m, fmaxf(fmaxf(v.x, v.y), fmaxf(v.z, v.w)));
    }
#pragma unroll
    for (int o = 16; o; o >>= 1) {
        s += __shfl_xor_sync(0xffffffffu, s, o);
        m = fmaxf(m, __shfl_xor_sync(0xffffffffu, m, o));
    }
    __shared__ float ss[8], sm[8];
    const int w = threadIdx.x >> 5, l = threadIdx.x & 31;
    if (l == 0) { ss[w] = s; sm[w] = m; }
    __syncthreads();
    if (threadIdx.x == 0) {
        float ts = 0.0f, tm = -3.4e38f;
#pragma unroll
        for (int i = 0; i < 8; i++) { ts += ss[i]; tm = fmaxf(tm, sm[i]); }
        g_psum[blockIdx.x] = ts;
        g_pmax[blockIdx.x] = tm;
    }
}

// ---------------------------------------------------------------------------
// Kernel 2: channel attention MLP (tiny). 1 block, 256 threads.
// ---------------------------------------------------------------------------
__global__ void __launch_bounds__(256) att_kernel(
    const float* __restrict__ ck1b,   // [8,128]
    const float* __restrict__ ck1s,   // [8,128,8]
    const float* __restrict__ ck2b,   // [128,8]
    const float* __restrict__ ck2s,   // [128,8,8]
    const float* __restrict__ convw)  // [128]
{
    __shared__ float s_val[512];            // [src(2)][pair(256)]
    __shared__ float s_silu[512];
    __shared__ float s_bas[512][GBASES];
    __shared__ float s_h1silu[32];          // [src][b][r]
    __shared__ float s_h1bas[32][GBASES];
    __shared__ float s_out[512];

    const int tid = threadIdx.x;

    // phase 0: reduce pooling partials
    {
        float ts = 0.0f, tm = -3.4e38f;
#pragma unroll
        for (int k = 0; k < NCHUNK; k++) {
            ts += g_psum[tid * NCHUNK + k];
            tm = fmaxf(tm, g_pmax[tid * NCHUNK + k]);
        }
        s_val[tid]       = ts * (1.0f / (float)S_SZ);  // y_avg
        s_val[256 + tid] = tm;                          // y_max
    }
    __syncthreads();

    // phase 1: silu + bases for all 512 pooled values
    for (int q = tid; q < 512; q += 256) {
        float v = s_val[q];
        s_silu[q] = siluf(v);
        bspline8(v, s_bas[q]);
    }
    __syncthreads();

    // phase 2: layer 1 -> h1 (32 tasks: src x b x r)
    if (tid < 32) {
        const int src = tid >> 4, b = (tid >> 3) & 1, r = tid & 7;
        const int base = src * 256 + b * 128;
        float acc = 0.0f;
        for (int i = 0; i < C_SZ; i++) {
            const int q = base + i;
            acc += s_silu[q] * ck1b[r * C_SZ + i];
            const float* sw = ck1s + (r * C_SZ + i) * GBASES;
#pragma unroll
            for (int g = 0; g < GBASES; g++) acc += s_bas[q][g] * sw[g];
        }
        const float hv = fmaxf(acc, 0.0f);
        s_h1silu[tid] = siluf(hv);
        bspline8(hv, s_h1bas[tid]);
    }
    __syncthreads();

    // phase 3: layer 2 (512 tasks: src x b x c)
    for (int q = tid; q < 512; q += 256) {
        const int src = q >> 8, b = (q >> 7) & 1, c = q & 127;
        float acc = 0.0f;
#pragma unroll
        for (int r = 0; r < 8; r++) {
            const int hq = src * 16 + b * 8 + r;
            acc += s_h1silu[hq] * ck2b[c * 8 + r];
            const float* sw = ck2s + (c * 8 + r) * GBASES;
#pragma unroll
            for (int g = 0; g < GBASES; g++) acc += s_h1bas[hq][g] * sw[g];
        }
        s_out[q] = acc;
    }
    __syncthreads();

    // phase 4: combine avg+max, sigmoid, and fold in conv_w
    {
        const float a = sigmoidf_(s_out[tid] + s_out[256 + tid]);
        g_att[tid] = a;
        g_wc[tid]  = a * convw[tid & 127];
    }
}

// ---------------------------------------------------------------------------
// Kernel 3: fused spatial pass — WARP-CONTIGUOUS 512B segments (R7, proven:
// 78.7us, 77.4% DRAM). Tile = 128 voxels x 128 channels. 512 threads =
// 16 warps: warp w owns channels [8w, 8w+8), lane l covers float4 lane l.
// Every LDG/STG: one warp moves 512 B contiguous from ONE channel.
// Register tile va[8] (x * channel_att) survives both barriers.
// ---------------------------------------------------------------------------
__global__ void __launch_bounds__(512, 2) fused_kernel(
    const float* __restrict__ x,
    const float* __restrict__ skb,   // [1]
    const float* __restrict__ sks,   // [8]
    float* __restrict__ out)
{
    __shared__ float4 wred[16][TILE_V4];             // 8 KB partial y_spatial
    __shared__ __align__(16) float satts[TILE_VOX];  // per-voxel spatial att

    const int b    = blockIdx.x >> 11;               // TILES_PER_B = 2048
    const int tile = blockIdx.x & (TILES_PER_B - 1);
    const int w    = threadIdx.x >> 5;               // warp 0..15
    const int l    = threadIdx.x & 31;               // float4 lane

    const size_t sbase4 = (size_t)tile * TILE_V4;    // float4 offset in plane
    const float4* xp = (const float4*)x;
    float4* op = (float4*)out;

    float4 va[8];                                     // x * channel_att (regs)
    float4 ws = make_float4(0.f, 0.f, 0.f, 0.f);
    const int cbase = w * 8;
#pragma unroll
    for (int k = 0; k < 8; k++) {
        const int pair = b * C_SZ + cbase + k;
        const float4 v = __ldcs(&xp[((size_t)pair << 16) + sbase4 + (size_t)l]);
        const float a  = g_att[pair];                 // uniform per warp
        const float wc = g_wc[pair];
        va[k] = make_float4(v.x * a, v.y * a, v.z * a, v.w * a);
        ws.x += v.x * wc; ws.y += v.y * wc; ws.z += v.z * wc; ws.w += v.w * wc;
    }
    wred[w][l] = ws;
    __syncthreads();

    // 128 threads: one voxel each — reduce 16 partials, 1->1 KAN spline.
    if (threadIdx.x < TILE_VOX) {
        const int vox = threadIdx.x;
        const int l4  = vox >> 2, j = vox & 3;
        float y = 0.0f;
#pragma unroll
        for (int p = 0; p < 16; p++) y += ((const float*)&wred[p][l4])[j];

        float bas[GBASES];
        bspline8(y, bas);
        float acc = siluf(y) * skb[0];
#pragma unroll
        for (int g = 0; g < GBASES; g++) acc += bas[g] * sks[g];
        satts[vox] = sigmoidf_(acc);
    }
    __syncthreads();

    const float4 sa = ((const float4*)satts)[l];
#pragma unroll
    for (int k = 0; k < 8; k++) {
        const int pair = b * C_SZ + cbase + k;
        __stcs(&op[((size_t)pair << 16) + sbase4 + (size_t)l],
               make_float4(va[k].x * sa.x, va[k].y * sa.y,
                           va[k].z * sa.z, va[k].w * sa.w));
    }
}

// ---------------------------------------------------------------------------
// Launch
// ---------------------------------------------------------------------------
extern "C" void kernel_launch(void* const* d_in, const int* in_sizes, int n_in,
                              void* d_out, int out_size) {
    const float* x     = (const float*)d_in[0];
    const float* ck1b  = (const float*)d_in[1];
    const float* ck1s  = (const float*)d_in[2];
    const float* ck2b  = (const float*)d_in[3];
    const float* ck2s  = (const float*)d_in[4];
    const float* convw = (const float*)d_in[5];
    const float* skb   = (const float*)d_in[6];
    const float* sks   = (const float*)d_in[7];
    float* out = (float*)d_out;

    pool_kernel<<<NPAIR * NCHUNK, 256>>>(x);
    att_kernel<<<1, 256>>>(ck1b, ck1s, ck2b, ck2s, convw);
    fused_kernel<<<B_SZ * TILES_PER_B, 512>>>(x, skb, sks, out);
}

// round 9
// speedup vs baseline: 1.3810x; 1.1637x over previous
#include <cuda_runtime.h>
#include <math.h>

// ---------------------------------------------------------------------------
// Problem constants (shapes fixed by setup_inputs)
// ---------------------------------------------------------------------------
#define B_SZ   2
#define C_SZ   128
#define S_SZ   262144          // 64*64*64 voxels per (b,c)
#define NPAIR  (B_SZ * C_SZ)   // 256
#define NCHUNK 8
#define GBASES 8               // GRID_SIZE + SPLINE_ORDER = 5 + 3

#define TILE_VOX 128                   // voxels per fused tile
#define TILE_V4  32                    // float4 lanes per tile
#define TILES_PER_B (S_SZ / TILE_VOX)  // 2048

// Scratch (no device allocation allowed)
__device__ float g_psum[NPAIR * NCHUNK];
__device__ float g_pmax[NPAIR * NCHUNK];
__device__ float g_att[NPAIR];   // sigmoid channel attention per (b,c)
__device__ float g_wc[NPAIR];    // att * conv_w  per (b,c)

// ---------------------------------------------------------------------------
// Cox-de Boor B-spline bases, k=3, grid = arange(-3,9)*0.4 - 1  (12 knots).
// Uniform grid -> FDIV replaced by multiply with compile-time reciprocals.
// ---------------------------------------------------------------------------
__device__ __forceinline__ void bspline8(float x, float* __restrict__ out) {
    float grid[12];
#pragma unroll
    for (int i = 0; i < 12; i++) grid[i] = (float)(i - 3) * 0.4f - 1.0f;
    float b[11];
#pragma unroll
    for (int j = 0; j < 11; j++)
        b[j] = (x >= grid[j] && x < grid[j + 1]) ? 1.0f : 0.0f;
    const float inv[3] = {2.5f, 1.25f, 1.0f / 1.2f};
#pragma unroll
    for (int j = 1; j <= 3; j++) {
        const float r = inv[j - 1];
#pragma unroll
        for (int m = 0; m < 11; m++) {
            if (m < 11 - j) {
                b[m] = (x - grid[m]) * r * b[m]
                     + (grid[m + j + 1] - x) * r * b[m + 1];
            }
        }
    }
#pragma unroll
    for (int g = 0; g < GBASES; g++) out[g] = b[g];
}

__device__ __forceinline__ float siluf(float v) { return v * (1.0f / (1.0f + __expf(-v))); }
__device__ __forceinline__ float sigmoidf_(float v) { return 1.0f / (1.0f + __expf(-v)); }

// ---------------------------------------------------------------------------
// Kernel 1: per-(b,c) partial sum/max pooling. 27 regs, ~84% DRAM. PROVEN.
// ---------------------------------------------------------------------------
__global__ void __launch_bounds__(256) pool_kernel(const float* __restrict__ x) {
    const int pair  = blockIdx.x >> 3;
    const int chunk = blockIdx.x & 7;
    const float4* p = (const float4*)(x + (size_t)pair * S_SZ + (size_t)chunk * (S_SZ / NCHUNK));

    float s = 0.0f, m = -3.4e38f;
#pragma unroll 4
    for (int it = 0; it < (S_SZ / NCHUNK / 4) / 256; it++) {
        float4 v = __ldcs(&p[it * 256 + threadIdx.x]);
        s += (v.x + v.y) + (v.z + v.w);
        m = fmaxf(m, fmaxf(fmaxf(v.x, v.y), fmaxf(v.z, v.w)));
    }
#pragma unroll
    for (int o = 16; o; o >>= 1) {
        s += __shfl_xor_sync(0xffffffffu, s, o);
        m = fmaxf(m, __shfl_xor_sync(0xffffffffu, m, o));
    }
    __shared__ float ss[8], sm[8];
    const int w = threadIdx.x >> 5, l = threadIdx.x & 31;
    if (l == 0) { ss[w] = s; sm[w] = m; }
    __syncthreads();
    if (threadIdx.x == 0) {
        float ts = 0.0f, tm = -3.4e38f;
#pragma unroll
        for (int i = 0; i < 8; i++) { ts += ss[i]; tm = fmaxf(tm, sm[i]); }
        g_psum[blockIdx.x] = ts;
        g_pmax[blockIdx.x] = tm;
    }
}

// ---------------------------------------------------------------------------
// Kernel 2: channel attention MLP. 1 block, 256 threads — now with phase 2
// parallelized over ALL 256 threads (32 tasks x 8 lanes, shfl reduce) and
// float4-vectorized weight fetches so DRAM latency is MLP-hidden.
// ---------------------------------------------------------------------------
__global__ void __launch_bounds__(256) att_kernel(
    const float* __restrict__ ck1b,   // [8,128]
    const float* __restrict__ ck1s,   // [8,128,8]
    const float* __restrict__ ck2b,   // [128,8]
    const float* __restrict__ ck2s,   // [128,8,8]
    const float* __restrict__ convw)  // [128]
{
    __shared__ float s_val[512];            // [src(2)][pair(256)]
    __shared__ float s_silu[512];
    __shared__ float s_bas[512][GBASES];
    __shared__ float s_h1silu[32];          // [src][b][r]
    __shared__ float s_h1bas[32][GBASES];
    __shared__ float s_out[512];

    const int tid = threadIdx.x;

    // phase 0: reduce pooling partials
    {
        float ts = 0.0f, tm = -3.4e38f;
#pragma unroll
        for (int k = 0; k < NCHUNK; k++) {
            ts += g_psum[tid * NCHUNK + k];
            tm = fmaxf(tm, g_pmax[tid * NCHUNK + k]);
        }
        s_val[tid]       = ts * (1.0f / (float)S_SZ);  // y_avg
        s_val[256 + tid] = tm;                          // y_max
    }
    __syncthreads();

    // phase 1: silu + bases for all 512 pooled values
    for (int q = tid; q < 512; q += 256) {
        float v = s_val[q];
        s_silu[q] = siluf(v);
        bspline8(v, s_bas[q]);
    }
    __syncthreads();

    // phase 2: layer 1 -> h1. 32 tasks (src x b x r) x 8 lanes; each lane
    // covers 16 of the 128 input channels; weights fetched as float4.
    {
        const int task = tid >> 3;                 // 0..31
        const int j    = tid & 7;                  // lane within task
        const int src  = task >> 4, b = (task >> 3) & 1, r = task & 7;
        const int base = src * 256 + b * 128;
        float acc = 0.0f;
#pragma unroll
        for (int ii = 0; ii < 16; ii++) {
            const int i = j + ii * 8;
            const int q = base + i;
            acc += s_silu[q] * ck1b[r * C_SZ + i];
            const float4* sw = (const float4*)(ck1s + (r * C_SZ + i) * GBASES);
            const float4 a0 = sw[0], a1 = sw[1];
            acc += s_bas[q][0] * a0.x + s_bas[q][1] * a0.y
                 + s_bas[q][2] * a0.z + s_bas[q][3] * a0.w
                 + s_bas[q][4] * a1.x + s_bas[q][5] * a1.y
                 + s_bas[q][6] * a1.z + s_bas[q][7] * a1.w;
        }
        // reduce the 8 lanes of each task (8-lane groups are warp-aligned)
#pragma unroll
        for (int o = 4; o; o >>= 1) acc += __shfl_xor_sync(0xffffffffu, acc, o);
        if (j == 0) {
            const float hv = fmaxf(acc, 0.0f);
            s_h1silu[task] = siluf(hv);
            bspline8(hv, s_h1bas[task]);
        }
    }
    __syncthreads();

    // phase 3: layer 2 (512 tasks: src x b x c), float4 weight fetches.
    for (int q = tid; q < 512; q += 256) {
        const int src = q >> 8, b = (q >> 7) & 1, c = q & 127;
        float acc = 0.0f;
#pragma unroll
        for (int r = 0; r < 8; r++) {
            const int hq = src * 16 + b * 8 + r;
            acc += s_h1silu[hq] * ck2b[c * 8 + r];
            const float4* sw = (const float4*)(ck2s + (c * 8 + r) * GBASES);
            const float4 a0 = sw[0], a1 = sw[1];
            acc += s_h1bas[hq][0] * a0.x + s_h1bas[hq][1] * a0.y
                 + s_h1bas[hq][2] * a0.z + s_h1bas[hq][3] * a0.w
                 + s_h1bas[hq][4] * a1.x + s_h1bas[hq][5] * a1.y
                 + s_h1bas[hq][6] * a1.z + s_h1bas[hq][7] * a1.w;
        }
        s_out[q] = acc;
    }
    __syncthreads();

    // phase 4: combine avg+max, sigmoid, and fold in conv_w
    {
        const float a = sigmoidf_(s_out[tid] + s_out[256 + tid]);
        g_att[tid] = a;
        g_wc[tid]  = a * convw[tid & 127];
    }
}

// ---------------------------------------------------------------------------
// Kernel 3: fused spatial pass — WARP-CONTIGUOUS 512B segments (R7, proven:
// 78.7us, 77.4% DRAM). Tile = 128 voxels x 128 channels. 512 threads =
// 16 warps: warp w owns channels [8w, 8w+8), lane l covers float4 lane l.
// ---------------------------------------------------------------------------
__global__ void __launch_bounds__(512, 2) fused_kernel(
    const float* __restrict__ x,
    const float* __restrict__ skb,   // [1]
    const float* __restrict__ sks,   // [8]
    float* __restrict__ out)
{
    __shared__ float4 wred[16][TILE_V4];             // 8 KB partial y_spatial
    __shared__ __align__(16) float satts[TILE_VOX];  // per-voxel spatial att

    const int b    = blockIdx.x >> 11;               // TILES_PER_B = 2048
    const int tile = blockIdx.x & (TILES_PER_B - 1);
    const int w    = threadIdx.x >> 5;               // warp 0..15
    const int l    = threadIdx.x & 31;               // float4 lane

    const size_t sbase4 = (size_t)tile * TILE_V4;    // float4 offset in plane
    const float4* xp = (const float4*)x;
    float4* op = (float4*)out;

    float4 va[8];                                     // x * channel_att (regs)
    float4 ws = make_float4(0.f, 0.f, 0.f, 0.f);
    const int cbase = w * 8;
#pragma unroll
    for (int k = 0; k < 8; k++) {
        const int pair = b * C_SZ + cbase + k;
        const float4 v = __ldcs(&xp[((size_t)pair << 16) + sbase4 + (size_t)l]);
        const float a  = g_att[pair];                 // uniform per warp
        const float wc = g_wc[pair];
        va[k] = make_float4(v.x * a, v.y * a, v.z * a, v.w * a);
        ws.x += v.x * wc; ws.y += v.y * wc; ws.z += v.z * wc; ws.w += v.w * wc;
    }
    wred[w][l] = ws;
    __syncthreads();

    // 128 threads: one voxel each — reduce 16 partials, 1->1 KAN spline.
    if (threadIdx.x < TILE_VOX) {
        const int vox = threadIdx.x;
        const int l4  = vox >> 2, j = vox & 3;
        float y = 0.0f;
#pragma unroll
        for (int p = 0; p < 16; p++) y += ((const float*)&wred[p][l4])[j];

        float bas[GBASES];
        bspline8(y, bas);
        float acc = siluf(y) * skb[0];
#pragma unroll
        for (int g = 0; g < GBASES; g++) acc += bas[g] * sks[g];
        satts[vox] = sigmoidf_(acc);
    }
    __syncthreads();

    const float4 sa = ((const float4*)satts)[l];
#pragma unroll
    for (int k = 0; k < 8; k++) {
        const int pair = b * C_SZ + cbase + k;
        __stcs(&op[((size_t)pair << 16) + sbase4 + (size_t)l],
               make_float4(va[k].x * sa.x, va[k].y * sa.y,
                           va[k].z * sa.z, va[k].w * sa.w));
    }
}

// ---------------------------------------------------------------------------
// Launch
// ---------------------------------------------------------------------------
extern "C" void kernel_launch(void* const* d_in, const int* in_sizes, int n_in,
                              void* d_out, int out_size) {
    const float* x     = (const float*)d_in[0];
    const float* ck1b  = (const float*)d_in[1];
    const float* ck1s  = (const float*)d_in[2];
    const float* ck2b  = (const float*)d_in[3];
    const float* ck2s  = (const float*)d_in[4];
    const float* convw = (const float*)d_in[5];
    const float* skb   = (const float*)d_in[6];
    const float* sks   = (const float*)d_in[7];
    float* out = (float*)d_out;

    pool_kernel<<<NPAIR * NCHUNK, 256>>>(x);
    att_kernel<<<1, 256>>>(ck1b, ck1s, ck2b, ck2s, convw);
    fused_kernel<<<B_SZ * TILES_PER_B, 512>>>(x, skb, sks, out);
}